// round 5
// baseline (speedup 1.0000x reference)
#include <cuda_runtime.h>
#include <cuda_bf16.h>
#include <cstdint>

// ---------------------------------------------------------------------------
// Problem constants
// ---------------------------------------------------------------------------
#define D_MODEL 1024
#define NHEAD   16
#define HDIM    64
#define TXT_LEN 226
#define CHUNKS  4
#define SEQ_TXT 904
#define VID_LEN 3328
#define CHUNK_VID 1024
#define T_ATTN  1250
#define M_ATTN  5000
#define SEQ_SSM 4232
#define ATTN_SCALE 0.125f
#define NCHUNK  34

// ---------------------------------------------------------------------------
// Scratch (static __device__)
// ---------------------------------------------------------------------------
__device__ float g_curp [5242880];
__device__ float g_qkv  [15360000];
__device__ float g_qt   [5120000];
__device__ float g_kt   [5120000];
__device__ float g_vt   [5120000];
__device__ float g_attnp[5242880];
__device__ float g_proj [5120000];
__device__ float g_emb  [4333568];
__device__ float g_embp [4456448];
__device__ float g_u    [4333568];
__device__ float g_hloc [4333568];
__device__ float g_hp   [4456448];
__device__ float g_y    [4333568];
__device__ float g_emb2 [4333568];
__device__ float g_revp [4456448];
__device__ float g_carry[34816];
__device__ float g_wqkv[3145728];
__device__ float g_bqkv[3072];
__device__ float g_wo  [1048576];
__device__ float g_win [1048576];
__device__ float g_wout[1048576];

__device__ __forceinline__ float tf32_rna(float x) {
  float r;
  asm("cvt.rna.tf32.f32 %0, %1;" : "=f"(r) : "f"(x));
  return r;
}

// A-fragment permuted offset for element (r, c) of an Mx1024 matrix.
__device__ __forceinline__ size_t aperm_off(int r, int c) {
  const int rb = r >> 7, rl = r & 127;
  const int kt = c >> 4, cl = c & 15;
  const int g  = rl >> 4;
  const int j  = ((rl >> 3) & 1) | (((cl >> 2) & 1) << 1);
  const int lane = ((rl & 7) << 2) | (cl & 3);
  return ((size_t)(rb * 64 + kt)) * 2048 + (((g << 1) + (cl >> 3)) << 7) +
         (lane << 2) + j;
}

// B-fragment permuted offset for element (k, c) of a 1024xN weight matrix.
__device__ __forceinline__ size_t bperm_off(int k, int c) {
  const int nb = c >> 7, kt = k >> 4;
  const int n8 = (c >> 3) & 15;
  const int kb = (k >> 3) & 1;
  const int j  = (k >> 2) & 1;
  const int lane = ((c & 7) << 2) | (k & 3);
  return ((size_t)(nb * 64 + kt)) * 2048 + (((n8 << 1) + kb) << 6) +
         (lane << 1) + j;
}

__device__ __forceinline__ void cp16(uint32_t s, const void* g) {
  asm volatile("cp.async.cg.shared.global [%0], [%1], 16;" :: "r"(s), "l"(g));
}
__device__ __forceinline__ void cp16z(uint32_t s, const void* g, int n) {
  asm volatile("cp.async.cg.shared.global [%0], [%1], 16, %2;" :: "r"(s), "l"(g), "r"(n));
}

// ---------------------------------------------------------------------------
// Weight packing
// ---------------------------------------------------------------------------
__global__ void pack_qkv_perm_kernel(const float* __restrict__ Wq,
                                     const float* __restrict__ Wk,
                                     const float* __restrict__ Wv,
                                     float* __restrict__ dst) {
  const int c = blockIdx.x * 256 + threadIdx.x;
  const int k = blockIdx.y;
  const float* W = (c < 1024) ? Wq : (c < 2048) ? Wk : Wv;
  dst[bperm_off(k, c)] = tf32_rna(W[(size_t)k * 1024 + (c & 1023)]);
}

__global__ void pack_bias_kernel(const float* __restrict__ bq,
                                 const float* __restrict__ bk,
                                 const float* __restrict__ bv,
                                 float* __restrict__ bp) {
  const int i = blockIdx.x * 256 + threadIdx.x;
  if (i < 1024) { bp[i] = bq[i]; bp[1024 + i] = bk[i]; bp[2048 + i] = bv[i]; }
}

__global__ void pack_b_perm_kernel(const float* __restrict__ W,
                                   float* __restrict__ dst) {
  const int c = blockIdx.x * 256 + threadIdx.x;
  const int k = blockIdx.y;
  dst[bperm_off(k, c)] = tf32_rna(W[(size_t)k * 1024 + c]);
}

// ---------------------------------------------------------------------------
// TF32 GEMM, 128x256 block tile, 64x64 warp tile, cp.async 3-stage.
// ---------------------------------------------------------------------------
#define STAGES 3
__global__ void __launch_bounds__(256, 1) tf32_gemm_perm(
    const float* __restrict__ Ap, const float* __restrict__ Bp,
    const float* __restrict__ bias, float* __restrict__ C,
    int M, int N) {
  __shared__ float As[STAGES][2048];   // 8 KB / stage
  __shared__ float Bs[STAGES][4096];   // 16 KB / stage
  const int tid = threadIdx.x;
  const int warp = tid >> 5, lane = tid & 31;
  const int wmg = (warp & 1) << 2;     // A row-group base (g = wmg + mi)
  const int wn  = (warp >> 1) << 6;    // warp col base (0..192)
  const int bchunk = wn >> 7;          // 0/1
  const int n8base = (wn & 127) >> 3;  // 0/8
  const int grp = lane >> 2, gcc = lane & 3;
  const int rb = blockIdx.y, nb = blockIdx.x;
  const float* Abase = Ap + (size_t)rb * 64 * 2048;
  const float* B0 = Bp + (size_t)(nb * 2) * 64 * 2048;
  const float* B1 = B0 + 64 * 2048;
  const uint32_t sA = (uint32_t)__cvta_generic_to_shared(&As[0][0]);
  const uint32_t sB = (uint32_t)__cvta_generic_to_shared(&Bs[0][0]);

  float acc[4][8][4];
#pragma unroll
  for (int mi = 0; mi < 4; mi++)
#pragma unroll
    for (int ni = 0; ni < 8; ni++)
#pragma unroll
      for (int j = 0; j < 4; j++) acc[mi][ni][j] = 0.f;

  auto issue = [&](int kt, int s) {
    const float* ga  = Abase + (size_t)kt * 2048;
    const float* gb0 = B0 + (size_t)kt * 2048;
    const float* gb1 = B1 + (size_t)kt * 2048;
    const uint32_t da = sA + s * 8192 + tid * 16;
    const uint32_t db = sB + s * 16384 + tid * 16;
    cp16(da,         ga + tid * 4);
    cp16(da + 4096,  ga + 1024 + tid * 4);
    cp16(db,         gb0 + tid * 4);
    cp16(db + 4096,  gb0 + 1024 + tid * 4);
    cp16(db + 8192,  gb1 + tid * 4);
    cp16(db + 12288, gb1 + 1024 + tid * 4);
    asm volatile("cp.async.commit_group;");
  };

  issue(0, 0);
  issue(1, 1);

  int s = 0;
  for (int kt = 0; kt < 64; kt++) {
    if (kt < 62) { asm volatile("cp.async.wait_group 1;"); }
    else         { asm volatile("cp.async.wait_group 0;"); }
    __syncthreads();
    if (kt + 2 < 64) issue(kt + 2, (kt + 2) % STAGES);

    const float4* a4 = reinterpret_cast<const float4*>(As[s]);
    const float2* b2 = reinterpret_cast<const float2*>(Bs[s]);
#pragma unroll
    for (int kb = 0; kb < 2; kb++) {
      float4 af[4];
      float2 bf[8];
#pragma unroll
      for (int mi = 0; mi < 4; mi++)
        af[mi] = a4[((((wmg + mi) << 1) + kb) << 5) + lane];
#pragma unroll
      for (int ni = 0; ni < 8; ni++)
        bf[ni] = b2[bchunk * 1024 + ((((n8base + ni) << 1) + kb) << 5) + lane];
#pragma unroll
      for (int mi = 0; mi < 4; mi++) {
        const uint32_t a0 = __float_as_uint(af[mi].x);
        const uint32_t a1 = __float_as_uint(af[mi].y);
        const uint32_t a2 = __float_as_uint(af[mi].z);
        const uint32_t a3 = __float_as_uint(af[mi].w);
#pragma unroll
        for (int ni = 0; ni < 8; ni++) {
          asm volatile(
              "mma.sync.aligned.m16n8k8.row.col.f32.tf32.tf32.f32 "
              "{%0,%1,%2,%3}, {%4,%5,%6,%7}, {%8,%9}, {%0,%1,%2,%3};"
              : "+f"(acc[mi][ni][0]), "+f"(acc[mi][ni][1]),
                "+f"(acc[mi][ni][2]), "+f"(acc[mi][ni][3])
              : "r"(a0), "r"(a1), "r"(a2), "r"(a3),
                "r"(__float_as_uint(bf[ni].x)), "r"(__float_as_uint(bf[ni].y)));
        }
      }
    }
    s = (s + 1) % STAGES;
  }

  const int row0 = rb * 128 + wmg * 16;   // wmg*16 = (warp&1)*64
  const int col0 = nb * 256 + wn;
#pragma unroll
  for (int mi = 0; mi < 4; mi++) {
    const int row = row0 + mi * 16 + grp;
#pragma unroll
    for (int ni = 0; ni < 8; ni++) {
      const int col = col0 + ni * 8 + (gcc << 1);
      float b0 = 0.f, b1 = 0.f;
      if (bias) { b0 = __ldg(bias + col); b1 = __ldg(bias + col + 1); }
      if (row < M) {
        float2 o; o.x = acc[mi][ni][0] + b0; o.y = acc[mi][ni][1] + b1;
        *reinterpret_cast<float2*>(C + (size_t)row * N + col) = o;
      }
      if (row + 8 < M) {
        float2 o; o.x = acc[mi][ni][2] + b0; o.y = acc[mi][ni][3] + b1;
        *reinterpret_cast<float2*>(C + (size_t)(row + 8) * N + col) = o;
      }
    }
  }
}

// ---------------------------------------------------------------------------
// Gather -> permuted cur
// ---------------------------------------------------------------------------
__global__ void gather_cur_perm_kernel(const float* __restrict__ vid,
                                       const float* __restrict__ txt,
                                       float* __restrict__ curp) {
  const int c = blockIdx.x * 256 + threadIdx.x;
  const int m = blockIdx.y;
  const int bc = m / T_ATTN;
  const int t  = m - bc * T_ATTN;
  const float v = (t < TXT_LEN)
      ? txt[((size_t)(bc * TXT_LEN + t)) * D_MODEL + c]
      : vid[((size_t)(bc * 768 + (t - TXT_LEN))) * D_MODEL + c];
  curp[aperm_off(m, c)] = tf32_rna(v);
}

// ---------------------------------------------------------------------------
// LayerNorm + RoPE + transpose
// ---------------------------------------------------------------------------
__device__ __forceinline__ void norm_rope_one(const float* __restrict__ src,
                                              const float* __restrict__ w,
                                              const float* __restrict__ b,
                                              float* __restrict__ dst, int t) {
  float x[64];
  float s = 0.f, ss = 0.f;
#pragma unroll
  for (int d = 0; d < 64; d++) {
    const float a = src[d];
    x[d] = a; s += a; ss += a * a;
  }
  const float mu  = s * (1.f / 64.f);
  const float var = ss * (1.f / 64.f) - mu * mu;
  const float rr  = rsqrtf(var + 1e-6f);
#pragma unroll
  for (int d = 0; d < 64; d++) x[d] = (x[d] - mu) * rr * w[d] + b[d];

  if (t >= TXT_LEN) {
    const int p = t - TXT_LEN;
    const float fpos = (float)(p >> 8);
    const int rem = p & 255;
    const float hpos = (float)(rem >> 4);
    const float wpos = (float)(rem & 15);
#pragma unroll
    for (int i = 0; i < 8; i++) {
      const float ang = fpos * __powf(10000.f, -(float)i * 0.125f);
      float sn, cs; sincosf(ang, &sn, &cs);
      const float x1 = x[i], x2 = x[8 + i];
      x[i]     = x1 * cs - x2 * sn;
      x[8 + i] = x1 * sn + x2 * cs;
    }
#pragma unroll
    for (int i = 0; i < 12; i++) {
      const float ang = hpos * __powf(10000.f, -(float)i * (1.f / 12.f));
      float sn, cs; sincosf(ang, &sn, &cs);
      const float x1 = x[16 + i], x2 = x[28 + i];
      x[16 + i] = x1 * cs - x2 * sn;
      x[28 + i] = x1 * sn + x2 * cs;
    }
#pragma unroll
    for (int i = 0; i < 12; i++) {
      const float ang = wpos * __powf(10000.f, -(float)i * (1.f / 12.f));
      float sn, cs; sincosf(ang, &sn, &cs);
      const float x1 = x[40 + i], x2 = x[52 + i];
      x[40 + i] = x1 * cs - x2 * sn;
      x[52 + i] = x1 * sn + x2 * cs;
    }
  }
#pragma unroll
  for (int d = 0; d < 64; d += 4)
    *reinterpret_cast<float4*>(dst + d) =
        make_float4(tf32_rna(x[d]), tf32_rna(x[d+1]), tf32_rna(x[d+2]), tf32_rna(x[d+3]));
}

__global__ void qkv_prep_kernel(const float* __restrict__ qkv,
                                const float* __restrict__ qw, const float* __restrict__ qb,
                                const float* __restrict__ kw, const float* __restrict__ kb,
                                float* __restrict__ qt, float* __restrict__ kt,
                                float* __restrict__ vt) {
  const int idx = blockIdx.x * blockDim.x + threadIdx.x;
  if (idx >= M_ATTN * NHEAD) return;
  const int m = idx >> 4;
  const int h = idx & 15;
  const int bc = m / T_ATTN;
  const int t  = m - bc * T_ATTN;
  const size_t src = (size_t)m * 3072 + h * HDIM;
  const size_t dst = ((size_t)(bc * NHEAD + h) * T_ATTN + t) * HDIM;
  norm_rope_one(qkv + src,        qw, qb, qt + dst, t);
  norm_rope_one(qkv + src + 1024, kw, kb, kt + dst, t);
#pragma unroll
  for (int d = 0; d < 64; d += 4) {
    const float4 v4 = *reinterpret_cast<const float4*>(qkv + src + 2048 + d);
    *reinterpret_cast<float4*>(vt + dst + d) =
        make_float4(tf32_rna(v4.x), tf32_rna(v4.y), tf32_rna(v4.z), tf32_rna(v4.w));
  }
}

// ---------------------------------------------------------------------------
// Flash attention tf32 with cp.async double-buffered K/V
// ---------------------------------------------------------------------------
#define FS 68
#define FA_TILE (64 * FS)
#define FA_SMEM ((6 * FA_TILE + 192) * 4)

__global__ void __launch_bounds__(256) flash_tf32_kernel(
    const float* __restrict__ Qt, const float* __restrict__ Kt,
    const float* __restrict__ Vt, float* __restrict__ Outp) {
  extern __shared__ float sm[];
  float* Qs = sm;
  float* KsB[2] = {sm + FA_TILE, sm + 2 * FA_TILE};
  float* VsB[2] = {sm + 3 * FA_TILE, sm + 4 * FA_TILE};
  float* Ss = sm + 5 * FA_TILE;
  float* sm_m  = sm + 6 * FA_TILE;
  float* sm_l  = sm_m + 64;
  float* sm_sc = sm_m + 128;

  const int mat = blockIdx.y;
  const int q0  = blockIdx.x * 64;
  const int tid = threadIdx.x;
  const int warp = tid >> 5;
  const int lane = tid & 31;
  const int gr = lane >> 2;
  const int gc = lane & 3;
  const int wm = (warp & 3) * 16;
  const int wn = (warp >> 2) * 32;

  const float* Qb = Qt + (size_t)mat * T_ATTN * HDIM;
  const float* Kb = Kt + (size_t)mat * T_ATTN * HDIM;
  const float* Vb = Vt + (size_t)mat * T_ATTN * HDIM;

  const int ldr  = tid >> 2;
  const int ldd  = (tid & 3) << 4;

  auto load_kv = [&](int k0, int buf) {
    const int gk = k0 + ldr;
    const int sz = (gk < T_ATTN) ? 16 : 0;
    const int gks = (gk < T_ATTN) ? gk : 0;
    const float* kp = Kb + (size_t)gks * HDIM + ldd;
    const float* vp = Vb + (size_t)gks * HDIM + ldd;
    const uint32_t dk = (uint32_t)__cvta_generic_to_shared(&KsB[buf][ldr * FS + ldd]);
    const uint32_t dv = (uint32_t)__cvta_generic_to_shared(&VsB[buf][ldr * FS + ldd]);
#pragma unroll
    for (int i = 0; i < 16; i += 4) {
      cp16z(dk + i * 4, kp + i, sz);
      cp16z(dv + i * 4, vp + i, sz);
    }
    asm volatile("cp.async.commit_group;");
  };

  if (tid < 64) { sm_m[tid] = -1e30f; sm_l[tid] = 0.f; }

  load_kv(0, 0);

  {
    const int gq = q0 + ldr;
#pragma unroll
    for (int i = 0; i < 16; i += 4) {
      float4 v4 = make_float4(0.f, 0.f, 0.f, 0.f);
      if (gq < T_ATTN)
        v4 = *reinterpret_cast<const float4*>(Qb + (size_t)gq * HDIM + ldd + i);
      *reinterpret_cast<float4*>(&Qs[ldr * FS + ldd + i]) = v4;
    }
  }
  __syncthreads();

  uint32_t qf[8][4];
#pragma unroll
  for (int kb = 0; kb < 8; kb++) {
    const int base = (wm + gr) * FS + kb * 8 + gc;
    qf[kb][0] = __float_as_uint(Qs[base]);
    qf[kb][1] = __float_as_uint(Qs[base + 8 * FS]);
    qf[kb][2] = __float_as_uint(Qs[base + 4]);
    qf[kb][3] = __float_as_uint(Qs[base + 8 * FS + 4]);
  }

  float acc[4][4];
#pragma unroll
  for (int ni = 0; ni < 4; ni++)
#pragma unroll
    for (int j = 0; j < 4; j++) acc[ni][j] = 0.f;

  const int NT = (T_ATTN + 63) >> 6;   // 20
  for (int it = 0; it < NT; it++) {
    asm volatile("cp.async.wait_group 0;");
    __syncthreads();
    if (it + 1 < NT) load_kv((it + 1) * 64, (it + 1) & 1);

    const float* Ks = KsB[it & 1];
    const float* Vs = VsB[it & 1];
    const int k0 = it * 64;

    float sacc[4][4];
#pragma unroll
    for (int ni = 0; ni < 4; ni++)
#pragma unroll
      for (int j = 0; j < 4; j++) sacc[ni][j] = 0.f;
#pragma unroll
    for (int kb = 0; kb < 8; kb++) {
      uint32_t bf[4][2];
#pragma unroll
      for (int ni = 0; ni < 4; ni++) {
        const int kbase = (wn + ni * 8 + gr) * FS + kb * 8 + gc;
        bf[ni][0] = __float_as_uint(Ks[kbase]);
        bf[ni][1] = __float_as_uint(Ks[kbase + 4]);
      }
#pragma unroll
      for (int ni = 0; ni < 4; ni++) {
        asm volatile(
            "mma.sync.aligned.m16n8k8.row.col.f32.tf32.tf32.f32 "
            "{%0,%1,%2,%3}, {%4,%5,%6,%7}, {%8,%9}, {%0,%1,%2,%3};"
            : "+f"(sacc[ni][0]), "+f"(sacc[ni][1]),
              "+f"(sacc[ni][2]), "+f"(sacc[ni][3])
            : "r"(qf[kb][0]), "r"(qf[kb][1]), "r"(qf[kb][2]), "r"(qf[kb][3]),
              "r"(bf[ni][0]), "r"(bf[ni][1]));
      }
    }

#pragma unroll
    for (int ni = 0; ni < 4; ni++) {
      const int col = wn + ni * 8 + (gc << 1);
      const int gk  = k0 + col;
      float2 s0, s1;
      s0.x = (gk     < T_ATTN) ? sacc[ni][0] * ATTN_SCALE : -1e30f;
      s0.y = (gk + 1 < T_ATTN) ? sacc[ni][1] * ATTN_SCALE : -1e30f;
      s1.x = (gk     < T_ATTN) ? sacc[ni][2] * ATTN_SCALE : -1e30f;
      s1.y = (gk + 1 < T_ATTN) ? sacc[ni][3] * ATTN_SCALE : -1e30f;
      *reinterpret_cast<float2*>(&Ss[(wm + gr) * FS + col])     = s0;
      *reinterpret_cast<float2*>(&Ss[(wm + 8 + gr) * FS + col]) = s1;
    }
    __syncthreads();

    {
      const int row = tid >> 2;
      const int qq  = tid & 3;
      float* rp = &Ss[row * FS + qq * 16];
      float v[16];
#pragma unroll
      for (int i = 0; i < 16; i += 4) {
        const float4 t4 = *reinterpret_cast<const float4*>(rp + i);
        v[i] = t4.x; v[i+1] = t4.y; v[i+2] = t4.z; v[i+3] = t4.w;
      }
      float mx = v[0];
#pragma unroll
      for (int i = 1; i < 16; i++) mx = fmaxf(mx, v[i]);
      mx = fmaxf(mx, __shfl_xor_sync(0xffffffffu, mx, 1));
      mx = fmaxf(mx, __shfl_xor_sync(0xffffffffu, mx, 2));
      const float m_old = sm_m[row];
      const float m_new = fmaxf(m_old, mx);
      const float sc = __expf(m_old - m_new);
      float sum = 0.f;
#pragma unroll
      for (int i = 0; i < 16; i++) {
        const float p = tf32_rna(__expf(v[i] - m_new));
        v[i] = p; sum += p;
      }
#pragma unroll
      for (int i = 0; i < 16; i += 4)
        *reinterpret_cast<float4*>(rp + i) = make_float4(v[i], v[i+1], v[i+2], v[i+3]);
      sum += __shfl_xor_sync(0xffffffffu, sum, 1);
      sum += __shfl_xor_sync(0xffffffffu, sum, 2);
      if (qq == 0) {
        sm_sc[row] = sc;
        sm_m[row]  = m_new;
        sm_l[row]  = sm_l[row] * sc + sum;
      }
    }
    __syncthreads();

    {
      const float sc0 = sm_sc[wm + gr];
      const float sc1 = sm_sc[wm + 8 + gr];
#pragma unroll
      for (int ni = 0; ni < 4; ni++) {
        acc[ni][0] *= sc0; acc[ni][1] *= sc0;
        acc[ni][2] *= sc1; acc[ni][3] *= sc1;
      }
#pragma unroll
      for (int kb = 0; kb < 8; kb++) {
        uint32_t af[4];
        const int abase = (wm + gr) * FS + kb * 8 + gc;
        af[0] = __float_as_uint(Ss[abase]);
        af[1] = __float_as_uint(Ss[abase + 8 * FS]);
        af[2] = __float_as_uint(Ss[abase + 4]);
        af[3] = __float_as_uint(Ss[abase + 8 * FS + 4]);
        uint32_t bf[4][2];
#pragma unroll
        for (int ni = 0; ni < 4; ni++) {
          const int vbase = (kb * 8 + gc) * FS + wn + ni * 8 + gr;
          bf[ni][0] = __float_as_uint(Vs[vbase]);
          bf[ni][1] = __float_as_uint(Vs[vbase + 4 * FS]);
        }
#pragma unroll
        for (int ni = 0; ni < 4; ni++) {
          asm volatile(
              "mma.sync.aligned.m16n8k8.row.col.f32.tf32.tf32.f32 "
              "{%0,%1,%2,%3}, {%4,%5,%6,%7}, {%8,%9}, {%0,%1,%2,%3};"
              : "+f"(acc[ni][0]), "+f"(acc[ni][1]),
                "+f"(acc[ni][2]), "+f"(acc[ni][3])
              : "r"(af[0]), "r"(af[1]), "r"(af[2]), "r"(af[3]),
                "r"(bf[ni][0]), "r"(bf[ni][1]));
        }
      }
    }
    __syncthreads();
  }

  const int bc = mat >> 4;
  const int h  = mat & 15;
  const float inv0 = 1.f / sm_l[wm + gr];
  const float inv1 = 1.f / sm_l[wm + 8 + gr];
  const int r0 = q0 + wm + gr;
  const int r1 = r0 + 8;
#pragma unroll
  for (int ni = 0; ni < 4; ni++) {
    const int col = h * HDIM + wn + ni * 8 + (gc << 1);
    if (r0 < T_ATTN) {
      const int gm = bc * T_ATTN + r0;
      Outp[aperm_off(gm, col)]     = tf32_rna(acc[ni][0] * inv0);
      Outp[aperm_off(gm, col + 1)] = tf32_rna(acc[ni][1] * inv0);
    }
    if (r1 < T_ATTN) {
      const int gm = bc * T_ATTN + r1;
      Outp[aperm_off(gm, col)]     = tf32_rna(acc[ni][2] * inv1);
      Outp[aperm_off(gm, col + 1)] = tf32_rna(acc[ni][3] * inv1);
    }
  }
}

// ---------------------------------------------------------------------------
// build emb
// ---------------------------------------------------------------------------
__global__ void build_emb_kernel(const float* __restrict__ proj,
                                 float* __restrict__ emb,
                                 float* __restrict__ embp) {
  const int idx = blockIdx.x * blockDim.x + threadIdx.x;
  if (idx >= SEQ_SSM * 256) return;
  const int i  = idx >> 8;
  const int d4 = (idx & 255) << 2;
  float4 o;
  if (i < SEQ_TXT) {
    const int c = i / TXT_LEN;
    const int t = i - c * TXT_LEN;
    o = *reinterpret_cast<const float4*>(proj + ((size_t)(c * T_ATTN + t)) * D_MODEL + d4);
  } else {
    const int p = i - SEQ_TXT;
    float4 acc = make_float4(0.f, 0.f, 0.f, 0.f);
    int cnt = 0;
#pragma unroll
    for (int c = 0; c < 4; c++) {
      const int j = p - c * 768;
      if (j >= 0 && j < CHUNK_VID) {
        const float4 v4 = *reinterpret_cast<const float4*>(
            proj + ((size_t)(c * T_ATTN + TXT_LEN + j)) * D_MODEL + d4);
        acc.x += v4.x; acc.y += v4.y; acc.z += v4.z; acc.w += v4.w;
        cnt++;
      }
    }
    const float inv = 1.f / (float)cnt;
    o.x = acc.x * inv; o.y = acc.y * inv; o.z = acc.z * inv; o.w = acc.w * inv;
  }
  *reinterpret_cast<float4*>(emb + (size_t)i * D_MODEL + d4) = o;
  embp[aperm_off(i, d4 + 0)] = tf32_rna(o.x);
  embp[aperm_off(i, d4 + 1)] = tf32_rna(o.y);
  embp[aperm_off(i, d4 + 2)] = tf32_rna(o.z);
  embp[aperm_off(i, d4 + 3)] = tf32_rna(o.w);
}

// ---------------------------------------------------------------------------
// Parallel SSM scan
// ---------------------------------------------------------------------------
__global__ void scan_pass1_kernel(const float* __restrict__ u,
                                  const float* __restrict__ gate,
                                  float* __restrict__ hloc,
                                  float* __restrict__ carry) {
  const int d = blockIdx.x * 256 + threadIdx.x;
  const int c = blockIdx.y;
  const float a = 1.f / (1.f + expf(-gate[d]));
  const int t0 = c * 128;
  const int t1 = (t0 + 128 < SEQ_SSM) ? (t0 + 128) : SEQ_SSM;
  float hv = 0.f;
  for (int t = t0; t < t1; t++) {
    hv = fmaf(a, hv, u[(size_t)t * D_MODEL + d]);
    hloc[(size_t)t * D_MODEL + d] = hv;
  }
  carry[c * 1024 + d] = hv;
}

__global__ void scan_pass2_kernel(const float* __restrict__ gate,
                                  float* __restrict__ carry) {
  const int d = blockIdx.x * 256 + threadIdx.x;
  const float a = 1.f / (1.f + expf(-gate[d]));
  const float a128 = __powf(a, 128.f);
  float s = 0.f;
  for (int c = 0; c < NCHUNK; c++) {
    const float cv = carry[c * 1024 + d];
    carry[c * 1024 + d] = s;
    s = a128 * s + cv;
  }
}

__global__ void scan_pass3_kernel(const float* __restrict__ hloc,
                                  const float* __restrict__ gate,
                                  const float* __restrict__ carry,
                                  float* __restrict__ hp) {
  const int d = blockIdx.x * 256 + threadIdx.x;
  const int c = blockIdx.y;
  const float a = 1.f / (1.f + expf(-gate[d]));
  const float cin = carry[c * 1024 + d];
  const int t0 = c * 128;
  const int t1 = (t0 + 128 < SEQ_SSM) ? (t0 + 128) : SEQ_SSM;
  float p = a;
  for (int t = t0; t < t1; t++) {
    const float hv = hloc[(size_t)t * D_MODEL + d] + p * cin;
    p *= a;
    hp[aperm_off(t, d)] = tf32_rna(hv);
  }
}

// ---------------------------------------------------------------------------
// gates / reverse / final
// ---------------------------------------------------------------------------
__global__ void gate_add_kernel(const float* __restrict__ base, const float* __restrict__ y,
                                const float* __restrict__ gt, const float* __restrict__ gv,
                                float* __restrict__ out) {
  const int idx = blockIdx.x * blockDim.x + threadIdx.x;
  if (idx >= SEQ_SSM * 256) return;
  const int i  = idx >> 8;
  const int d4 = (idx & 255) << 2;
  const float* g = (i < SEQ_TXT) ? gt : gv;
  const float4 b4 = *reinterpret_cast<const float4*>(base + (size_t)i * D_MODEL + d4);
  const float4 y4 = *reinterpret_cast<const float4*>(y + (size_t)i * D_MODEL + d4);
  float4 o;
  o.x = b4.x + tanhf(g[d4 + 0]) * y4.x;
  o.y = b4.y + tanhf(g[d4 + 1]) * y4.y;
  o.z = b4.z + tanhf(g[d4 + 2]) * y4.z;
  o.w = b4.w + tanhf(g[d4 + 3]) * y4.w;
  *reinterpret_cast<float4*>(out + (size_t)i * D_MODEL + d4) = o;
}

__device__ __forceinline__ int rev_map(int i) {
  if (i < SEQ_TXT) {
    const int c = i / TXT_LEN;
    return (3 - c) * TXT_LEN + (i - c * TXT_LEN);
  }
  return 5135 - i;
}

__global__ void rev_perm_kernel(const float* __restrict__ src, float* __restrict__ dstp) {
  const int c = blockIdx.x * 256 + threadIdx.x;
  const int i = blockIdx.y;
  const int s = rev_map(i);
  dstp[aperm_off(i, c)] = tf32_rna(src[(size_t)s * D_MODEL + c]);
}

__global__ void final_kernel(const float* __restrict__ emb2, const float* __restrict__ y2,
                             const float* __restrict__ gt, const float* __restrict__ gv,
                             float* __restrict__ out) {
  const int idx = blockIdx.x * blockDim.x + threadIdx.x;
  if (idx >= SEQ_SSM * 256) return;
  const int i  = idx >> 8;
  const int d4 = (idx & 255) << 2;
  const int s = rev_map(i);
  const float* g = (i < SEQ_TXT) ? gt : gv;
  const float4 e4 = *reinterpret_cast<const float4*>(emb2 + (size_t)i * D_MODEL + d4);
  const float4 y4 = *reinterpret_cast<const float4*>(y2 + (size_t)s * D_MODEL + d4);
  float4 o;
  o.x = e4.x + tanhf(g[d4 + 0]) * y4.x;
  o.y = e4.y + tanhf(g[d4 + 1]) * y4.y;
  o.z = e4.z + tanhf(g[d4 + 2]) * y4.z;
  o.w = e4.w + tanhf(g[d4 + 3]) * y4.w;
  const int dst = (i < SEQ_TXT) ? (VID_LEN + i) : (i - SEQ_TXT);
  *reinterpret_cast<float4*>(out + (size_t)dst * D_MODEL + d4) = o;
}

// ---------------------------------------------------------------------------
// Launch
// ---------------------------------------------------------------------------
static float* sym_addr(const void* symbol) {
  void* p = nullptr;
  cudaGetSymbolAddress(&p, symbol);
  return (float*)p;
}

extern "C" void kernel_launch(void* const* d_in, const int* in_sizes, int n_in,
                              void* d_out, int out_size) {
  (void)in_sizes; (void)n_in; (void)out_size;
  const float* vid   = (const float*)d_in[0];
  const float* txt   = (const float*)d_in[1];
  const float* Wq    = (const float*)d_in[2];
  const float* bq    = (const float*)d_in[3];
  const float* Wk    = (const float*)d_in[4];
  const float* bk    = (const float*)d_in[5];
  const float* Wv    = (const float*)d_in[6];
  const float* bv    = (const float*)d_in[7];
  const float* Wo    = (const float*)d_in[8];
  const float* bo    = (const float*)d_in[9];
  const float* qn_w  = (const float*)d_in[10];
  const float* qn_b  = (const float*)d_in[11];
  const float* kn_w  = (const float*)d_in[12];
  const float* kn_b  = (const float*)d_in[13];
  const float* Win   = (const float*)d_in[14];
  const float* Wout  = (const float*)d_in[15];
  const float* gate  = (const float*)d_in[16];
  const float* fg_t  = (const float*)d_in[17];
  const float* fg_v  = (const float*)d_in[18];
  const float* bg_t  = (const float*)d_in[19];
  const float* bg_v  = (const float*)d_in[20];
  float* out = (float*)d_out;

  float* curp  = sym_addr(g_curp);
  float* qkv   = sym_addr(g_qkv);
  float* qt    = sym_addr(g_qt);
  float* kt    = sym_addr(g_kt);
  float* vt    = sym_addr(g_vt);
  float* attnp = sym_addr(g_attnp);
  float* proj  = sym_addr(g_proj);
  float* emb   = sym_addr(g_emb);
  float* embp  = sym_addr(g_embp);
  float* u     = sym_addr(g_u);
  float* hloc  = sym_addr(g_hloc);
  float* hp    = sym_addr(g_hp);
  float* y     = sym_addr(g_y);
  float* emb2  = sym_addr(g_emb2);
  float* revp  = sym_addr(g_revp);
  float* carry = sym_addr(g_carry);
  float* wqkv  = sym_addr(g_wqkv);
  float* bqkv  = sym_addr(g_bqkv);
  float* wo_p  = sym_addr(g_wo);
  float* win_p  = sym_addr(g_win);
  float* wout_p = sym_addr(g_wout);

  cudaFuncSetAttribute(flash_tf32_kernel, cudaFuncAttributeMaxDynamicSharedMemorySize, FA_SMEM);

  pack_qkv_perm_kernel<<<dim3(12, 1024), 256>>>(Wq, Wk, Wv, wqkv);
  pack_bias_kernel<<<4, 256>>>(bq, bk, bv, bqkv);
  pack_b_perm_kernel<<<dim3(4, 1024), 256>>>(Wo, wo_p);
  pack_b_perm_kernel<<<dim3(4, 1024), 256>>>(Win, win_p);
  pack_b_perm_kernel<<<dim3(4, 1024), 256>>>(Wout, wout_p);

  gather_cur_perm_kernel<<<dim3(4, M_ATTN), 256>>>(vid, txt, curp);
  tf32_gemm_perm<<<dim3(12, 40), 256>>>(curp, wqkv, bqkv, qkv, M_ATTN, 3072);
  qkv_prep_kernel<<<(M_ATTN * NHEAD) / 128, 128>>>(qkv, qn_w, qn_b, kn_w, kn_b,
                                                   qt, kt, vt);
  flash_tf32_kernel<<<dim3(20, 64), 256, FA_SMEM>>>(qt, kt, vt, attnp);
  tf32_gemm_perm<<<dim3(4, 40), 256>>>(attnp, wo_p, bo, proj, M_ATTN, 1024);
  build_emb_kernel<<<SEQ_SSM, 256>>>(proj, emb, embp);

  tf32_gemm_perm<<<dim3(4, 34), 256>>>(embp, win_p, nullptr, u, SEQ_SSM, 1024);
  scan_pass1_kernel<<<dim3(4, NCHUNK), 256>>>(u, gate, hloc, carry);
  scan_pass2_kernel<<<4, 256>>>(gate, carry);
  scan_pass3_kernel<<<dim3(4, NCHUNK), 256>>>(hloc, gate, carry, hp);
  tf32_gemm_perm<<<dim3(4, 34), 256>>>(hp, wout_p, nullptr, y, SEQ_SSM, 1024);
  gate_add_kernel<<<SEQ_SSM, 256>>>(emb, y, fg_t, fg_v, emb2);

  rev_perm_kernel<<<dim3(4, SEQ_SSM), 256>>>(emb2, revp);
  tf32_gemm_perm<<<dim3(4, 34), 256>>>(revp, win_p, nullptr, u, SEQ_SSM, 1024);
  scan_pass1_kernel<<<dim3(4, NCHUNK), 256>>>(u, gate, hloc, carry);
  scan_pass2_kernel<<<4, 256>>>(gate, carry);
  scan_pass3_kernel<<<dim3(4, NCHUNK), 256>>>(hloc, gate, carry, hp);
  tf32_gemm_perm<<<dim3(4, 34), 256>>>(hp, wout_p, nullptr, y, SEQ_SSM, 1024);
  final_kernel<<<SEQ_SSM, 256>>>(emb2, y, bg_t, bg_v, out);
}

// round 6
// speedup vs baseline: 1.5885x; 1.5885x over previous
#include <cuda_runtime.h>
#include <cuda_bf16.h>
#include <cstdint>

// ---------------------------------------------------------------------------
// Problem constants
// ---------------------------------------------------------------------------
#define D_MODEL 1024
#define NHEAD   16
#define HDIM    64
#define TXT_LEN 226
#define CHUNKS  4
#define SEQ_TXT 904
#define VID_LEN 3328
#define CHUNK_VID 1024
#define T_ATTN  1250
#define M_ATTN  5000
#define SEQ_SSM 4232
#define ATTN_SCALE 0.125f
#define NCHUNK  34

// ---------------------------------------------------------------------------
// Scratch (static __device__)
// ---------------------------------------------------------------------------
__device__ float g_curp [5242880];
__device__ float g_qkv  [15360000];
__device__ float g_qt   [5120000];
__device__ float g_kt   [5120000];
__device__ float g_vt   [5120000];
__device__ float g_attnp[5242880];
__device__ float g_proj [5120000];
__device__ float g_emb  [4333568];
__device__ float g_embp [4456448];
__device__ float g_u    [4333568];
__device__ float g_hloc [4333568];
__device__ float g_hp   [4456448];
__device__ float g_y    [4333568];
__device__ float g_emb2 [4333568];
__device__ float g_revp [4456448];
__device__ float g_carry[34816];
__device__ float g_wqkv[3145728];
__device__ float g_bqkv[3072];
__device__ float g_wo  [1048576];
__device__ float g_win [1048576];
__device__ float g_wout[1048576];

__device__ __forceinline__ float tf32_rna(float x) {
  float r;
  asm("cvt.rna.tf32.f32 %0, %1;" : "=f"(r) : "f"(x));
  return r;
}

// A-fragment permuted offset for element (r, c) of an Mx1024 matrix.
__device__ __forceinline__ size_t aperm_off(int r, int c) {
  const int rb = r >> 7, rl = r & 127;
  const int kt = c >> 4, cl = c & 15;
  const int g  = rl >> 4;
  const int j  = ((rl >> 3) & 1) | (((cl >> 2) & 1) << 1);
  const int lane = ((rl & 7) << 2) | (cl & 3);
  return ((size_t)(rb * 64 + kt)) * 2048 + (((g << 1) + (cl >> 3)) << 7) +
         (lane << 2) + j;
}

// B-fragment permuted offset for element (k, c) of a 1024xN weight matrix.
__device__ __forceinline__ size_t bperm_off(int k, int c) {
  const int nb = c >> 7, kt = k >> 4;
  const int n8 = (c >> 3) & 15;
  const int kb = (k >> 3) & 1;
  const int j  = (k >> 2) & 1;
  const int lane = ((c & 7) << 2) | (k & 3);
  return ((size_t)(nb * 64 + kt)) * 2048 + (((n8 << 1) + kb) << 6) +
         (lane << 1) + j;
}

__device__ __forceinline__ void cp16(uint32_t s, const void* g) {
  asm volatile("cp.async.cg.shared.global [%0], [%1], 16;" :: "r"(s), "l"(g));
}
__device__ __forceinline__ void cp16z(uint32_t s, const void* g, int n) {
  asm volatile("cp.async.cg.shared.global [%0], [%1], 16, %2;" :: "r"(s), "l"(g), "r"(n));
}

// ---------------------------------------------------------------------------
// Weight packing
// ---------------------------------------------------------------------------
__global__ void pack_qkv_perm_kernel(const float* __restrict__ Wq,
                                     const float* __restrict__ Wk,
                                     const float* __restrict__ Wv,
                                     float* __restrict__ dst) {
  const int c = blockIdx.x * 256 + threadIdx.x;
  const int k = blockIdx.y;
  const float* W = (c < 1024) ? Wq : (c < 2048) ? Wk : Wv;
  dst[bperm_off(k, c)] = tf32_rna(W[(size_t)k * 1024 + (c & 1023)]);
}

__global__ void pack_bias_kernel(const float* __restrict__ bq,
                                 const float* __restrict__ bk,
                                 const float* __restrict__ bv,
                                 float* __restrict__ bp) {
  const int i = blockIdx.x * 256 + threadIdx.x;
  if (i < 1024) { bp[i] = bq[i]; bp[1024 + i] = bk[i]; bp[2048 + i] = bv[i]; }
}

__global__ void pack_b_perm_kernel(const float* __restrict__ W,
                                   float* __restrict__ dst) {
  const int c = blockIdx.x * 256 + threadIdx.x;
  const int k = blockIdx.y;
  dst[bperm_off(k, c)] = tf32_rna(W[(size_t)k * 1024 + c]);
}

// ---------------------------------------------------------------------------
// TF32 GEMM on fragment-permuted operands, cp.async 3-stage pipeline.
// Block tile 128x128x16, 8 warps (4 row-slabs x 2 col-halves). (R4 config)
// ---------------------------------------------------------------------------
#define STAGES 3
__global__ void __launch_bounds__(256) tf32_gemm_perm(
    const float* __restrict__ Ap, const float* __restrict__ Bp,
    const float* __restrict__ bias, float* __restrict__ C,
    int M, int N) {
  __shared__ float As[STAGES][2048];
  __shared__ float Bs[STAGES][2048];
  const int tid = threadIdx.x;
  const int warp = tid >> 5, lane = tid & 31;
  const int ws = warp & 3;
  const int wn = (warp >> 2) << 6;
  const int grp = lane >> 2, gcc = lane & 3;
  const int rb = blockIdx.y, nb = blockIdx.x;
  const float* Abase = Ap + (size_t)rb * 64 * 2048;
  const float* Bbase = Bp + (size_t)nb * 64 * 2048;
  const uint32_t sA = (uint32_t)__cvta_generic_to_shared(&As[0][0]);
  const uint32_t sB = (uint32_t)__cvta_generic_to_shared(&Bs[0][0]);

  float acc[2][8][4];
#pragma unroll
  for (int mi = 0; mi < 2; mi++)
#pragma unroll
    for (int ni = 0; ni < 8; ni++)
#pragma unroll
      for (int j = 0; j < 4; j++) acc[mi][ni][j] = 0.f;

  auto issue = [&](int kt, int s) {
    const float* ga = Abase + (size_t)kt * 2048;
    const float* gb = Bbase + (size_t)kt * 2048;
    const uint32_t da = sA + s * 8192 + tid * 16;
    const uint32_t db = sB + s * 8192 + tid * 16;
    cp16(da,        ga + tid * 4);
    cp16(da + 4096, ga + 1024 + tid * 4);
    cp16(db,        gb + tid * 4);
    cp16(db + 4096, gb + 1024 + tid * 4);
    asm volatile("cp.async.commit_group;");
  };

  issue(0, 0);
  issue(1, 1);

  int s = 0;
  for (int kt = 0; kt < 64; kt++) {
    if (kt < 62) { asm volatile("cp.async.wait_group 1;"); }
    else         { asm volatile("cp.async.wait_group 0;"); }
    __syncthreads();
    if (kt + 2 < 64) issue(kt + 2, (kt + 2) % STAGES);

    const float4* a4 = reinterpret_cast<const float4*>(As[s]);
    const float2* b2 = reinterpret_cast<const float2*>(Bs[s]);
#pragma unroll
    for (int kb = 0; kb < 2; kb++) {
      float4 af[2];
      float2 bf[8];
#pragma unroll
      for (int mi = 0; mi < 2; mi++)
        af[mi] = a4[((((ws << 1) + mi) * 2 + kb) << 5) + lane];
#pragma unroll
      for (int ni = 0; ni < 8; ni++)
        bf[ni] = b2[((((wn >> 3) + ni) * 2 + kb) << 5) + lane];
#pragma unroll
      for (int mi = 0; mi < 2; mi++) {
        const uint32_t a0 = __float_as_uint(af[mi].x);
        const uint32_t a1 = __float_as_uint(af[mi].y);
        const uint32_t a2 = __float_as_uint(af[mi].z);
        const uint32_t a3 = __float_as_uint(af[mi].w);
#pragma unroll
        for (int ni = 0; ni < 8; ni++) {
          asm volatile(
              "mma.sync.aligned.m16n8k8.row.col.f32.tf32.tf32.f32 "
              "{%0,%1,%2,%3}, {%4,%5,%6,%7}, {%8,%9}, {%0,%1,%2,%3};"
              : "+f"(acc[mi][ni][0]), "+f"(acc[mi][ni][1]),
                "+f"(acc[mi][ni][2]), "+f"(acc[mi][ni][3])
              : "r"(a0), "r"(a1), "r"(a2), "r"(a3),
                "r"(__float_as_uint(bf[ni].x)), "r"(__float_as_uint(bf[ni].y)));
        }
      }
    }
    s = (s + 1) % STAGES;
  }

  const int row0 = rb * 128 + ws * 32;
  const int col0 = nb * 128 + wn;
#pragma unroll
  for (int mi = 0; mi < 2; mi++) {
    const int row = row0 + mi * 16 + grp;
#pragma unroll
    for (int ni = 0; ni < 8; ni++) {
      const int col = col0 + ni * 8 + (gcc << 1);
      float b0 = 0.f, b1 = 0.f;
      if (bias) { b0 = __ldg(bias + col); b1 = __ldg(bias + col + 1); }
      if (row < M) {
        float2 o; o.x = acc[mi][ni][0] + b0; o.y = acc[mi][ni][1] + b1;
        *reinterpret_cast<float2*>(C + (size_t)row * N + col) = o;
      }
      if (row + 8 < M) {
        float2 o; o.x = acc[mi][ni][2] + b0; o.y = acc[mi][ni][3] + b1;
        *reinterpret_cast<float2*>(C + (size_t)(row + 8) * N + col) = o;
      }
    }
  }
}

// ---------------------------------------------------------------------------
// Gather -> permuted cur
// ---------------------------------------------------------------------------
__global__ void gather_cur_perm_kernel(const float* __restrict__ vid,
                                       const float* __restrict__ txt,
                                       float* __restrict__ curp) {
  const int c = blockIdx.x * 256 + threadIdx.x;
  const int m = blockIdx.y;
  const int bc = m / T_ATTN;
  const int t  = m - bc * T_ATTN;
  const float v = (t < TXT_LEN)
      ? txt[((size_t)(bc * TXT_LEN + t)) * D_MODEL + c]
      : vid[((size_t)(bc * 768 + (t - TXT_LEN))) * D_MODEL + c];
  curp[aperm_off(m, c)] = tf32_rna(v);
}

// ---------------------------------------------------------------------------
// LayerNorm + RoPE + transpose
// ---------------------------------------------------------------------------
__device__ __forceinline__ void norm_rope_one(const float* __restrict__ src,
                                              const float* __restrict__ w,
                                              const float* __restrict__ b,
                                              float* __restrict__ dst, int t) {
  float x[64];
  float s = 0.f, ss = 0.f;
#pragma unroll
  for (int d = 0; d < 64; d++) {
    const float a = src[d];
    x[d] = a; s += a; ss += a * a;
  }
  const float mu  = s * (1.f / 64.f);
  const float var = ss * (1.f / 64.f) - mu * mu;
  const float rr  = rsqrtf(var + 1e-6f);
#pragma unroll
  for (int d = 0; d < 64; d++) x[d] = (x[d] - mu) * rr * w[d] + b[d];

  if (t >= TXT_LEN) {
    const int p = t - TXT_LEN;
    const float fpos = (float)(p >> 8);
    const int rem = p & 255;
    const float hpos = (float)(rem >> 4);
    const float wpos = (float)(rem & 15);
#pragma unroll
    for (int i = 0; i < 8; i++) {
      const float ang = fpos * __powf(10000.f, -(float)i * 0.125f);
      float sn, cs; sincosf(ang, &sn, &cs);
      const float x1 = x[i], x2 = x[8 + i];
      x[i]     = x1 * cs - x2 * sn;
      x[8 + i] = x1 * sn + x2 * cs;
    }
#pragma unroll
    for (int i = 0; i < 12; i++) {
      const float ang = hpos * __powf(10000.f, -(float)i * (1.f / 12.f));
      float sn, cs; sincosf(ang, &sn, &cs);
      const float x1 = x[16 + i], x2 = x[28 + i];
      x[16 + i] = x1 * cs - x2 * sn;
      x[28 + i] = x1 * sn + x2 * cs;
    }
#pragma unroll
    for (int i = 0; i < 12; i++) {
      const float ang = wpos * __powf(10000.f, -(float)i * (1.f / 12.f));
      float sn, cs; sincosf(ang, &sn, &cs);
      const float x1 = x[40 + i], x2 = x[52 + i];
      x[40 + i] = x1 * cs - x2 * sn;
      x[52 + i] = x1 * sn + x2 * cs;
    }
  }
#pragma unroll
  for (int d = 0; d < 64; d += 4)
    *reinterpret_cast<float4*>(dst + d) =
        make_float4(tf32_rna(x[d]), tf32_rna(x[d+1]), tf32_rna(x[d+2]), tf32_rna(x[d+3]));
}

__global__ void qkv_prep_kernel(const float* __restrict__ qkv,
                                const float* __restrict__ qw, const float* __restrict__ qb,
                                const float* __restrict__ kw, const float* __restrict__ kb,
                                float* __restrict__ qt, float* __restrict__ kt,
                                float* __restrict__ vt) {
  const int idx = blockIdx.x * blockDim.x + threadIdx.x;
  if (idx >= M_ATTN * NHEAD) return;
  const int m = idx >> 4;
  const int h = idx & 15;
  const int bc = m / T_ATTN;
  const int t  = m - bc * T_ATTN;
  const size_t src = (size_t)m * 3072 + h * HDIM;
  const size_t dst = ((size_t)(bc * NHEAD + h) * T_ATTN + t) * HDIM;
  norm_rope_one(qkv + src,        qw, qb, qt + dst, t);
  norm_rope_one(qkv + src + 1024, kw, kb, kt + dst, t);
#pragma unroll
  for (int d = 0; d < 64; d += 4) {
    const float4 v4 = *reinterpret_cast<const float4*>(qkv + src + 2048 + d);
    *reinterpret_cast<float4*>(vt + dst + d) =
        make_float4(tf32_rna(v4.x), tf32_rna(v4.y), tf32_rna(v4.z), tf32_rna(v4.w));
  }
}

// ---------------------------------------------------------------------------
// Flash attention tf32 with cp.async double-buffered K/V (R5 version)
// ---------------------------------------------------------------------------
#define FS 68
#define FA_TILE (64 * FS)
#define FA_SMEM ((6 * FA_TILE + 192) * 4)

__global__ void __launch_bounds__(256) flash_tf32_kernel(
    const float* __restrict__ Qt, const float* __restrict__ Kt,
    const float* __restrict__ Vt, float* __restrict__ Outp) {
  extern __shared__ float sm[];
  float* Qs = sm;
  float* KsB[2] = {sm + FA_TILE, sm + 2 * FA_TILE};
  float* VsB[2] = {sm + 3 * FA_TILE, sm + 4 * FA_TILE};
  float* Ss = sm + 5 * FA_TILE;
  float* sm_m  = sm + 6 * FA_TILE;
  float* sm_l  = sm_m + 64;
  float* sm_sc = sm_m + 128;

  const int mat = blockIdx.y;
  const int q0  = blockIdx.x * 64;
  const int tid = threadIdx.x;
  const int warp = tid >> 5;
  const int lane = tid & 31;
  const int gr = lane >> 2;
  const int gc = lane & 3;
  const int wm = (warp & 3) * 16;
  const int wn = (warp >> 2) * 32;

  const float* Qb = Qt + (size_t)mat * T_ATTN * HDIM;
  const float* Kb = Kt + (size_t)mat * T_ATTN * HDIM;
  const float* Vb = Vt + (size_t)mat * T_ATTN * HDIM;

  const int ldr  = tid >> 2;
  const int ldd  = (tid & 3) << 4;

  auto load_kv = [&](int k0, int buf) {
    const int gk = k0 + ldr;
    const int sz = (gk < T_ATTN) ? 16 : 0;
    const int gks = (gk < T_ATTN) ? gk : 0;
    const float* kp = Kb + (size_t)gks * HDIM + ldd;
    const float* vp = Vb + (size_t)gks * HDIM + ldd;
    const uint32_t dk = (uint32_t)__cvta_generic_to_shared(&KsB[buf][ldr * FS + ldd]);
    const uint32_t dv = (uint32_t)__cvta_generic_to_shared(&VsB[buf][ldr * FS + ldd]);
#pragma unroll
    for (int i = 0; i < 16; i += 4) {
      cp16z(dk + i * 4, kp + i, sz);
      cp16z(dv + i * 4, vp + i, sz);
    }
    asm volatile("cp.async.commit_group;");
  };

  if (tid < 64) { sm_m[tid] = -1e30f; sm_l[tid] = 0.f; }

  load_kv(0, 0);

  {
    const int gq = q0 + ldr;
#pragma unroll
    for (int i = 0; i < 16; i += 4) {
      float4 v4 = make_float4(0.f, 0.f, 0.f, 0.f);
      if (gq < T_ATTN)
        v4 = *reinterpret_cast<const float4*>(Qb + (size_t)gq * HDIM + ldd + i);
      *reinterpret_cast<float4*>(&Qs[ldr * FS + ldd + i]) = v4;
    }
  }
  __syncthreads();

  uint32_t qf[8][4];
#pragma unroll
  for (int kb = 0; kb < 8; kb++) {
    const int base = (wm + gr) * FS + kb * 8 + gc;
    qf[kb][0] = __float_as_uint(Qs[base]);
    qf[kb][1] = __float_as_uint(Qs[base + 8 * FS]);
    qf[kb][2] = __float_as_uint(Qs[base + 4]);
    qf[kb][3] = __float_as_uint(Qs[base + 8 * FS + 4]);
  }

  float acc[4][4];
#pragma unroll
  for (int ni = 0; ni < 4; ni++)
#pragma unroll
    for (int j = 0; j < 4; j++) acc[ni][j] = 0.f;

  const int NT = (T_ATTN + 63) >> 6;
  for (int it = 0; it < NT; it++) {
    asm volatile("cp.async.wait_group 0;");
    __syncthreads();
    if (it + 1 < NT) load_kv((it + 1) * 64, (it + 1) & 1);

    const float* Ks = KsB[it & 1];
    const float* Vs = VsB[it & 1];
    const int k0 = it * 64;

    float sacc[4][4];
#pragma unroll
    for (int ni = 0; ni < 4; ni++)
#pragma unroll
      for (int j = 0; j < 4; j++) sacc[ni][j] = 0.f;
#pragma unroll
    for (int kb = 0; kb < 8; kb++) {
      uint32_t bf[4][2];
#pragma unroll
      for (int ni = 0; ni < 4; ni++) {
        const int kbase = (wn + ni * 8 + gr) * FS + kb * 8 + gc;
        bf[ni][0] = __float_as_uint(Ks[kbase]);
        bf[ni][1] = __float_as_uint(Ks[kbase + 4]);
      }
#pragma unroll
      for (int ni = 0; ni < 4; ni++) {
        asm volatile(
            "mma.sync.aligned.m16n8k8.row.col.f32.tf32.tf32.f32 "
            "{%0,%1,%2,%3}, {%4,%5,%6,%7}, {%8,%9}, {%0,%1,%2,%3};"
            : "+f"(sacc[ni][0]), "+f"(sacc[ni][1]),
              "+f"(sacc[ni][2]), "+f"(sacc[ni][3])
            : "r"(qf[kb][0]), "r"(qf[kb][1]), "r"(qf[kb][2]), "r"(qf[kb][3]),
              "r"(bf[ni][0]), "r"(bf[ni][1]));
      }
    }

#pragma unroll
    for (int ni = 0; ni < 4; ni++) {
      const int col = wn + ni * 8 + (gc << 1);
      const int gk  = k0 + col;
      float2 s0, s1;
      s0.x = (gk     < T_ATTN) ? sacc[ni][0] * ATTN_SCALE : -1e30f;
      s0.y = (gk + 1 < T_ATTN) ? sacc[ni][1] * ATTN_SCALE : -1e30f;
      s1.x = (gk     < T_ATTN) ? sacc[ni][2] * ATTN_SCALE : -1e30f;
      s1.y = (gk + 1 < T_ATTN) ? sacc[ni][3] * ATTN_SCALE : -1e30f;
      *reinterpret_cast<float2*>(&Ss[(wm + gr) * FS + col])     = s0;
      *reinterpret_cast<float2*>(&Ss[(wm + 8 + gr) * FS + col]) = s1;
    }
    __syncthreads();

    {
      const int row = tid >> 2;
      const int qq  = tid & 3;
      float* rp = &Ss[row * FS + qq * 16];
      float v[16];
#pragma unroll
      for (int i = 0; i < 16; i += 4) {
        const float4 t4 = *reinterpret_cast<const float4*>(rp + i);
        v[i] = t4.x; v[i+1] = t4.y; v[i+2] = t4.z; v[i+3] = t4.w;
      }
      float mx = v[0];
#pragma unroll
      for (int i = 1; i < 16; i++) mx = fmaxf(mx, v[i]);
      mx = fmaxf(mx, __shfl_xor_sync(0xffffffffu, mx, 1));
      mx = fmaxf(mx, __shfl_xor_sync(0xffffffffu, mx, 2));
      const float m_old = sm_m[row];
      const float m_new = fmaxf(m_old, mx);
      const float sc = __expf(m_old - m_new);
      float sum = 0.f;
#pragma unroll
      for (int i = 0; i < 16; i++) {
        const float p = tf32_rna(__expf(v[i] - m_new));
        v[i] = p; sum += p;
      }
#pragma unroll
      for (int i = 0; i < 16; i += 4)
        *reinterpret_cast<float4*>(rp + i) = make_float4(v[i], v[i+1], v[i+2], v[i+3]);
      sum += __shfl_xor_sync(0xffffffffu, sum, 1);
      sum += __shfl_xor_sync(0xffffffffu, sum, 2);
      if (qq == 0) {
        sm_sc[row] = sc;
        sm_m[row]  = m_new;
        sm_l[row]  = sm_l[row] * sc + sum;
      }
    }
    __syncthreads();

    {
      const float sc0 = sm_sc[wm + gr];
      const float sc1 = sm_sc[wm + 8 + gr];
#pragma unroll
      for (int ni = 0; ni < 4; ni++) {
        acc[ni][0] *= sc0; acc[ni][1] *= sc0;
        acc[ni][2] *= sc1; acc[ni][3] *= sc1;
      }
#pragma unroll
      for (int kb = 0; kb < 8; kb++) {
        uint32_t af[4];
        const int abase = (wm + gr) * FS + kb * 8 + gc;
        af[0] = __float_as_uint(Ss[abase]);
        af[1] = __float_as_uint(Ss[abase + 8 * FS]);
        af[2] = __float_as_uint(Ss[abase + 4]);
        af[3] = __float_as_uint(Ss[abase + 8 * FS + 4]);
        uint32_t bf[4][2];
#pragma unroll
        for (int ni = 0; ni < 4; ni++) {
          const int vbase = (kb * 8 + gc) * FS + wn + ni * 8 + gr;
          bf[ni][0] = __float_as_uint(Vs[vbase]);
          bf[ni][1] = __float_as_uint(Vs[vbase + 4 * FS]);
        }
#pragma unroll
        for (int ni = 0; ni < 4; ni++) {
          asm volatile(
              "mma.sync.aligned.m16n8k8.row.col.f32.tf32.tf32.f32 "
              "{%0,%1,%2,%3}, {%4,%5,%6,%7}, {%8,%9}, {%0,%1,%2,%3};"
              : "+f"(acc[ni][0]), "+f"(acc[ni][1]),
                "+f"(acc[ni][2]), "+f"(acc[ni][3])
              : "r"(af[0]), "r"(af[1]), "r"(af[2]), "r"(af[3]),
                "r"(bf[ni][0]), "r"(bf[ni][1]));
        }
      }
    }
    __syncthreads();
  }

  const int bc = mat >> 4;
  const int h  = mat & 15;
  const float inv0 = 1.f / sm_l[wm + gr];
  const float inv1 = 1.f / sm_l[wm + 8 + gr];
  const int r0 = q0 + wm + gr;
  const int r1 = r0 + 8;
#pragma unroll
  for (int ni = 0; ni < 4; ni++) {
    const int col = h * HDIM + wn + ni * 8 + (gc << 1);
    if (r0 < T_ATTN) {
      const int gm = bc * T_ATTN + r0;
      Outp[aperm_off(gm, col)]     = tf32_rna(acc[ni][0] * inv0);
      Outp[aperm_off(gm, col + 1)] = tf32_rna(acc[ni][1] * inv0);
    }
    if (r1 < T_ATTN) {
      const int gm = bc * T_ATTN + r1;
      Outp[aperm_off(gm, col)]     = tf32_rna(acc[ni][2] * inv1);
      Outp[aperm_off(gm, col + 1)] = tf32_rna(acc[ni][3] * inv1);
    }
  }
}

// ---------------------------------------------------------------------------
// build emb
// ---------------------------------------------------------------------------
__global__ void build_emb_kernel(const float* __restrict__ proj,
                                 float* __restrict__ emb,
                                 float* __restrict__ embp) {
  const int idx = blockIdx.x * blockDim.x + threadIdx.x;
  if (idx >= SEQ_SSM * 256) return;
  const int i  = idx >> 8;
  const int d4 = (idx & 255) << 2;
  float4 o;
  if (i < SEQ_TXT) {
    const int c = i / TXT_LEN;
    const int t = i - c * TXT_LEN;
    o = *reinterpret_cast<const float4*>(proj + ((size_t)(c * T_ATTN + t)) * D_MODEL + d4);
  } else {
    const int p = i - SEQ_TXT;
    float4 acc = make_float4(0.f, 0.f, 0.f, 0.f);
    int cnt = 0;
#pragma unroll
    for (int c = 0; c < 4; c++) {
      const int j = p - c * 768;
      if (j >= 0 && j < CHUNK_VID) {
        const float4 v4 = *reinterpret_cast<const float4*>(
            proj + ((size_t)(c * T_ATTN + TXT_LEN + j)) * D_MODEL + d4);
        acc.x += v4.x; acc.y += v4.y; acc.z += v4.z; acc.w += v4.w;
        cnt++;
      }
    }
    const float inv = 1.f / (float)cnt;
    o.x = acc.x * inv; o.y = acc.y * inv; o.z = acc.z * inv; o.w = acc.w * inv;
  }
  *reinterpret_cast<float4*>(emb + (size_t)i * D_MODEL + d4) = o;
  embp[aperm_off(i, d4 + 0)] = tf32_rna(o.x);
  embp[aperm_off(i, d4 + 1)] = tf32_rna(o.y);
  embp[aperm_off(i, d4 + 2)] = tf32_rna(o.z);
  embp[aperm_off(i, d4 + 3)] = tf32_rna(o.w);
}

// ---------------------------------------------------------------------------
// Parallel SSM scan
// ---------------------------------------------------------------------------
__global__ void scan_pass1_kernel(const float* __restrict__ u,
                                  const float* __restrict__ gate,
                                  float* __restrict__ hloc,
                                  float* __restrict__ carry) {
  const int d = blockIdx.x * 256 + threadIdx.x;
  const int c = blockIdx.y;
  const float a = 1.f / (1.f + expf(-gate[d]));
  const int t0 = c * 128;
  const int t1 = (t0 + 128 < SEQ_SSM) ? (t0 + 128) : SEQ_SSM;
  float hv = 0.f;
  for (int t = t0; t < t1; t++) {
    hv = fmaf(a, hv, u[(size_t)t * D_MODEL + d]);
    hloc[(size_t)t * D_MODEL + d] = hv;
  }
  carry[c * 1024 + d] = hv;
}

__global__ void scan_pass2_kernel(const float* __restrict__ gate,
                                  float* __restrict__ carry) {
  const int d = blockIdx.x * 256 + threadIdx.x;
  const float a = 1.f / (1.f + expf(-gate[d]));
  const float a128 = __powf(a, 128.f);
  float s = 0.f;
  for (int c = 0; c < NCHUNK; c++) {
    const float cv = carry[c * 1024 + d];
    carry[c * 1024 + d] = s;
    s = a128 * s + cv;
  }
}

__global__ void scan_pass3_kernel(const float* __restrict__ hloc,
                                  const float* __restrict__ gate,
                                  const float* __restrict__ carry,
                                  float* __restrict__ hp) {
  const int d = blockIdx.x * 256 + threadIdx.x;
  const int c = blockIdx.y;
  const float a = 1.f / (1.f + expf(-gate[d]));
  const float cin = carry[c * 1024 + d];
  const int t0 = c * 128;
  const int t1 = (t0 + 128 < SEQ_SSM) ? (t0 + 128) : SEQ_SSM;
  float p = a;
  for (int t = t0; t < t1; t++) {
    const float hv = hloc[(size_t)t * D_MODEL + d] + p * cin;
    p *= a;
    hp[aperm_off(t, d)] = tf32_rna(hv);
  }
}

// ---------------------------------------------------------------------------
// gates / reverse / final
// ---------------------------------------------------------------------------
__global__ void gate_add_kernel(const float* __restrict__ base, const float* __restrict__ y,
                                const float* __restrict__ gt, const float* __restrict__ gv,
                                float* __restrict__ out) {
  const int idx = blockIdx.x * blockDim.x + threadIdx.x;
  if (idx >= SEQ_SSM * 256) return;
  const int i  = idx >> 8;
  const int d4 = (idx & 255) << 2;
  const float* g = (i < SEQ_TXT) ? gt : gv;
  const float4 b4 = *reinterpret_cast<const float4*>(base + (size_t)i * D_MODEL + d4);
  const float4 y4 = *reinterpret_cast<const float4*>(y + (size_t)i * D_MODEL + d4);
  float4 o;
  o.x = b4.x + tanhf(g[d4 + 0]) * y4.x;
  o.y = b4.y + tanhf(g[d4 + 1]) * y4.y;
  o.z = b4.z + tanhf(g[d4 + 2]) * y4.z;
  o.w = b4.w + tanhf(g[d4 + 3]) * y4.w;
  *reinterpret_cast<float4*>(out + (size_t)i * D_MODEL + d4) = o;
}

__device__ __forceinline__ int rev_map(int i) {
  if (i < SEQ_TXT) {
    const int c = i / TXT_LEN;
    return (3 - c) * TXT_LEN + (i - c * TXT_LEN);
  }
  return 5135 - i;
}

__global__ void rev_perm_kernel(const float* __restrict__ src, float* __restrict__ dstp) {
  const int c = blockIdx.x * 256 + threadIdx.x;
  const int i = blockIdx.y;
  const int s = rev_map(i);
  dstp[aperm_off(i, c)] = tf32_rna(src[(size_t)s * D_MODEL + c]);
}

__global__ void final_kernel(const float* __restrict__ emb2, const float* __restrict__ y2,
                             const float* __restrict__ gt, const float* __restrict__ gv,
                             float* __restrict__ out) {
  const int idx = blockIdx.x * blockDim.x + threadIdx.x;
  if (idx >= SEQ_SSM * 256) return;
  const int i  = idx >> 8;
  const int d4 = (idx & 255) << 2;
  const int s = rev_map(i);
  const float* g = (i < SEQ_TXT) ? gt : gv;
  const float4 e4 = *reinterpret_cast<const float4*>(emb2 + (size_t)i * D_MODEL + d4);
  const float4 y4 = *reinterpret_cast<const float4*>(y2 + (size_t)s * D_MODEL + d4);
  float4 o;
  o.x = e4.x + tanhf(g[d4 + 0]) * y4.x;
  o.y = e4.y + tanhf(g[d4 + 1]) * y4.y;
  o.z = e4.z + tanhf(g[d4 + 2]) * y4.z;
  o.w = e4.w + tanhf(g[d4 + 3]) * y4.w;
  const int dst = (i < SEQ_TXT) ? (VID_LEN + i) : (i - SEQ_TXT);
  *reinterpret_cast<float4*>(out + (size_t)dst * D_MODEL + d4) = o;
}

// ---------------------------------------------------------------------------
// Launch
// ---------------------------------------------------------------------------
static float* sym_addr(const void* symbol) {
  void* p = nullptr;
  cudaGetSymbolAddress(&p, symbol);
  return (float*)p;
}

extern "C" void kernel_launch(void* const* d_in, const int* in_sizes, int n_in,
                              void* d_out, int out_size) {
  (void)in_sizes; (void)n_in; (void)out_size;
  const float* vid   = (const float*)d_in[0];
  const float* txt   = (const float*)d_in[1];
  const float* Wq    = (const float*)d_in[2];
  const float* bq    = (const float*)d_in[3];
  const float* Wk    = (const float*)d_in[4];
  const float* bk    = (const float*)d_in[5];
  const float* Wv    = (const float*)d_in[6];
  const float* bv    = (const float*)d_in[7];
  const float* Wo    = (const float*)d_in[8];
  const float* bo    = (const float*)d_in[9];
  const float* qn_w  = (const float*)d_in[10];
  const float* qn_b  = (const float*)d_in[11];
  const float* kn_w  = (const float*)d_in[12];
  const float* kn_b  = (const float*)d_in[13];
  const float* Win   = (const float*)d_in[14];
  const float* Wout  = (const float*)d_in[15];
  const float* gate  = (const float*)d_in[16];
  const float* fg_t  = (const float*)d_in[17];
  const float* fg_v  = (const float*)d_in[18];
  const float* bg_t  = (const float*)d_in[19];
  const float* bg_v  = (const float*)d_in[20];
  float* out = (float*)d_out;

  float* curp  = sym_addr(g_curp);
  float* qkv   = sym_addr(g_qkv);
  float* qt    = sym_addr(g_qt);
  float* kt    = sym_addr(g_kt);
  float* vt    = sym_addr(g_vt);
  float* attnp = sym_addr(g_attnp);
  float* proj  = sym_addr(g_proj);
  float* emb   = sym_addr(g_emb);
  float* embp  = sym_addr(g_embp);
  float* u     = sym_addr(g_u);
  float* hloc  = sym_addr(g_hloc);
  float* hp    = sym_addr(g_hp);
  float* y     = sym_addr(g_y);
  float* emb2  = sym_addr(g_emb2);
  float* revp  = sym_addr(g_revp);
  float* carry = sym_addr(g_carry);
  float* wqkv  = sym_addr(g_wqkv);
  float* bqkv  = sym_addr(g_bqkv);
  float* wo_p  = sym_addr(g_wo);
  float* win_p  = sym_addr(g_win);
  float* wout_p = sym_addr(g_wout);

  cudaFuncSetAttribute(flash_tf32_kernel, cudaFuncAttributeMaxDynamicSharedMemorySize, FA_SMEM);

  pack_qkv_perm_kernel<<<dim3(12, 1024), 256>>>(Wq, Wk, Wv, wqkv);
  pack_bias_kernel<<<4, 256>>>(bq, bk, bv, bqkv);
  pack_b_perm_kernel<<<dim3(4, 1024), 256>>>(Wo, wo_p);
  pack_b_perm_kernel<<<dim3(4, 1024), 256>>>(Win, win_p);
  pack_b_perm_kernel<<<dim3(4, 1024), 256>>>(Wout, wout_p);

  gather_cur_perm_kernel<<<dim3(4, M_ATTN), 256>>>(vid, txt, curp);
  tf32_gemm_perm<<<dim3(24, 40), 256>>>(curp, wqkv, bqkv, qkv, M_ATTN, 3072);
  qkv_prep_kernel<<<(M_ATTN * NHEAD) / 128, 128>>>(qkv, qn_w, qn_b, kn_w, kn_b,
                                                   qt, kt, vt);
  flash_tf32_kernel<<<dim3(20, 64), 256, FA_SMEM>>>(qt, kt, vt, attnp);
  tf32_gemm_perm<<<dim3(8, 40), 256>>>(attnp, wo_p, bo, proj, M_ATTN, 1024);
  build_emb_kernel<<<SEQ_SSM, 256>>>(proj, emb, embp);

  tf32_gemm_perm<<<dim3(8, 34), 256>>>(embp, win_p, nullptr, u, SEQ_SSM, 1024);
  scan_pass1_kernel<<<dim3(4, NCHUNK), 256>>>(u, gate, hloc, carry);
  scan_pass2_kernel<<<4, 256>>>(gate, carry);
  scan_pass3_kernel<<<dim3(4, NCHUNK), 256>>>(hloc, gate, carry, hp);
  tf32_gemm_perm<<<dim3(8, 34), 256>>>(hp, wout_p, nullptr, y, SEQ_SSM, 1024);
  gate_add_kernel<<<SEQ_SSM, 256>>>(emb, y, fg_t, fg_v, emb2);

  rev_perm_kernel<<<dim3(4, SEQ_SSM), 256>>>(emb2, revp);
  tf32_gemm_perm<<<dim3(8, 34), 256>>>(revp, win_p, nullptr, u, SEQ_SSM, 1024);
  scan_pass1_kernel<<<dim3(4, NCHUNK), 256>>>(u, gate, hloc, carry);
  scan_pass2_kernel<<<4, 256>>>(gate, carry);
  scan_pass3_kernel<<<dim3(4, NCHUNK), 256>>>(hloc, gate, carry, hp);
  tf32_gemm_perm<<<dim3(8, 34), 256>>>(hp, wout_p, nullptr, y, SEQ_SSM, 1024);
  final_kernel<<<SEQ_SSM, 256>>>(emb2, y, bg_t, bg_v, out);
}